// round 4
// baseline (speedup 1.0000x reference)
#include <cuda_runtime.h>
#include <cstdint>
#include <math.h>

// Problem dims
#define BB   128
#define TT   1024
#define II   256
#define HH   512
#define KTOT 768      // HH + II (combined K dimension: h-part then x-part)
#define KC   96       // k-chunk size (768 = 8 * 96)
#define NCHUNK 8
#define GRID 128      // CTAs; each owns 4 h-columns (16 gate rows)
#define NTHREADS 128  // 4 warps; warp w <-> local h-col w
#define NPAIR 64      // 128 batches as 64 f32x2 pairs

typedef unsigned long long ull;

// Scratch (static __device__ arrays: allocation-free kernel_launch)
__device__ float g_xT[(size_t)TT * II * BB];   // [t][i][b]  (134 MB)
__device__ float g_hT[2][HH * BB];             // [buf][k][b] (512 KB)
__device__ unsigned g_bar_count;               // monotonic arrivals
__device__ unsigned g_bar_gen;                 // generation counter

// ---------- packed fp32 helpers ----------
__device__ __forceinline__ void fma2(ull &d, ull a, ull b) {
    asm("fma.rn.f32x2 %0, %1, %2, %0;" : "+l"(d) : "l"(a), "l"(b));
}
__device__ __forceinline__ ull pack2(float lo, float hi) {
    ull r; asm("mov.b64 %0, {%1, %2};" : "=l"(r) : "f"(lo), "f"(hi)); return r;
}
__device__ __forceinline__ void unpack2(float &lo, float &hi, ull v) {
    asm("mov.b64 {%0, %1}, %2;" : "=f"(lo), "=f"(hi) : "l"(v));
}
// ---------- cp.async ----------
__device__ __forceinline__ void cp_async16(void* dst_smem, const void* src) {
    unsigned d = (unsigned)__cvta_generic_to_shared(dst_smem);
    asm volatile("cp.async.cg.shared.global [%0], [%1], 16;" :: "r"(d), "l"(src));
}
__device__ __forceinline__ void cp_commit() { asm volatile("cp.async.commit_group;"); }
template<int N> __device__ __forceinline__ void cp_wait() {
    asm volatile("cp.async.wait_group %0;" :: "n"(N));
}

__device__ __forceinline__ float sigf(float x) { return 1.0f / (1.0f + expf(-x)); }

// ---------- grid-wide barrier (monotonic count: no reset race) ----------
__device__ __forceinline__ void grid_barrier(unsigned target) {
    __syncthreads();
    __threadfence();   // make this CTA's hT stores visible device-wide
    if (threadIdx.x == 0) {
        unsigned a = atomicAdd(&g_bar_count, 1u) + 1u;
        if (a == (unsigned)GRID * target) {
            __threadfence();
            atomicAdd(&g_bar_gen, 1u);
        } else {
            while (*(volatile unsigned*)&g_bar_gen < target) { }
        }
        __threadfence();
    }
    __syncthreads();
}

// ---------- prep: transpose x -> xT[t][i][b], reset barrier ----------
__global__ void prep_kernel(const float* __restrict__ x) {
    __shared__ float tile[32][33];
    int t  = blockIdx.z;
    int i0 = blockIdx.x * 32;
    int b0 = blockIdx.y * 32;
    int tx = threadIdx.x, ty = threadIdx.y;
    if (blockIdx.x == 0 && blockIdx.y == 0 && blockIdx.z == 0 && tx == 0 && ty == 0) {
        g_bar_count = 0u; g_bar_gen = 0u;
    }
    #pragma unroll
    for (int j = 0; j < 4; j++) {
        int b = b0 + ty + j * 8;   // tile[b_local][i_local]
        tile[ty + j * 8][tx] = x[(size_t)b * (TT * II) + (size_t)t * II + i0 + tx];
    }
    __syncthreads();
    #pragma unroll
    for (int j = 0; j < 4; j++) {
        int i = i0 + ty + j * 8;
        g_xT[((size_t)t * II + i) * BB + b0 + tx] = tile[tx][ty + j * 8];
    }
}

// ---------- activation chunk loader: As[kk][pair] <- {hT | xT_t} ----------
__device__ __forceinline__ void load_chunk(ull* dst, int k0,
                                           const float* __restrict__ hsrc,
                                           const float* __restrict__ xsrc,
                                           int tid) {
    // 96 k-rows * 32 16B-units per row = 3072 units; 24 per thread
    #pragma unroll
    for (int u = 0; u < 24; u++) {
        int id = tid + u * NTHREADS;
        int kk = id >> 5;
        int pu = id & 31;
        int k  = k0 + kk;
        const float* src = (k < HH) ? (hsrc + k * BB + pu * 4)
                                    : (xsrc + (k - HH) * BB + pu * 4);
        cp_async16(dst + kk * NPAIR + pu * 2, src);
    }
}

// ---------- persistent LSTM kernel ----------
__global__ void __launch_bounds__(NTHREADS, 1) lstm_kernel(
    const float* __restrict__ W_ih, const float* __restrict__ W_hh,
    const float* __restrict__ b_ih, const float* __restrict__ b_hh,
    float* __restrict__ out)
{
    extern __shared__ char smem[];
    ull* W2s = (ull*)smem;                          // [16][768] dup-packed weights
    ull* As  = (ull*)(smem + 16 * KTOT * 8);        // [2][96][64] activation pairs

    const int tid = threadIdx.x;
    const int w   = tid >> 5;     // local h-col (warp id)
    const int l   = tid & 31;     // lane -> batch pairs l and l+32
    const int cta = blockIdx.x;
    const int ghc = cta * 4 + w;  // global h-col

    // Load weights once, duplicated into both f32x2 lanes.
    // row r = hcol*4 + gate ; global gate row n = gate*512 + cta*4 + hcol
    for (int idx = tid; idx < 16 * KTOT; idx += NTHREADS) {
        int r = idx / KTOT;
        int k = idx - r * KTOT;
        int gate = r & 3, hc = r >> 2;
        int n = gate * HH + cta * 4 + hc;
        float wv = (k < HH) ? W_hh[n * HH + k] : W_ih[n * II + (k - HH)];
        W2s[idx] = pack2(wv, wv);
    }

    float bias[4];
    #pragma unroll
    for (int g = 0; g < 4; g++) {
        int n = g * HH + ghc;
        bias[g] = b_ih[n] + b_hh[n];
    }

    // h0 = 0 (buffer 0, own slice)
    g_hT[0][ghc * BB + 2 * l]      = 0.f;
    g_hT[0][ghc * BB + 2 * l + 1]  = 0.f;

    float c0a = 0.f, c0b = 0.f, c1a = 0.f, c1b = 0.f;

    unsigned gen = 0;
    grid_barrier(++gen);   // hT buf0 zeroed everywhere

    const ull* Wbase = W2s + (w * 4) * KTOT;

    for (int t = 0; t < TT; t++) {
        const int rb = t & 1, wb = rb ^ 1;
        const float* hsrc = g_hT[rb];
        const float* xsrc = g_xT + (size_t)t * II * BB;

        ull acc[2][4];
        #pragma unroll
        for (int g = 0; g < 4; g++) {
            acc[0][g] = pack2(bias[g], bias[g]);
            acc[1][g] = acc[0][g];
        }

        load_chunk(As, 0, hsrc, xsrc, tid);   // prologue: chunk 0 -> buf 0
        cp_commit();

        for (int ci = 0; ci < NCHUNK; ci++) {
            if (ci + 1 < NCHUNK) {
                load_chunk(As + ((ci + 1) & 1) * (KC * NPAIR), (ci + 1) * KC,
                           hsrc, xsrc, tid);
                cp_commit();
                cp_wait<1>();
            } else {
                cp_wait<0>();
            }
            __syncthreads();  // all threads' copies for chunk ci landed

            const ull* Ab = As + (ci & 1) * (KC * NPAIR);
            const ull* Wr0 = Wbase + 0 * KTOT + ci * KC;
            const ull* Wr1 = Wbase + 1 * KTOT + ci * KC;
            const ull* Wr2 = Wbase + 2 * KTOT + ci * KC;
            const ull* Wr3 = Wbase + 3 * KTOT + ci * KC;
            #pragma unroll 4
            for (int kk = 0; kk < KC; kk++) {
                ull a0 = Ab[kk * NPAIR + l];
                ull a1 = Ab[kk * NPAIR + l + 32];
                ull w0 = Wr0[kk], w1 = Wr1[kk], w2 = Wr2[kk], w3 = Wr3[kk];
                fma2(acc[0][0], a0, w0); fma2(acc[1][0], a1, w0);
                fma2(acc[0][1], a0, w1); fma2(acc[1][1], a1, w1);
                fma2(acc[0][2], a0, w2); fma2(acc[1][2], a1, w2);
                fma2(acc[0][3], a0, w3); fma2(acc[1][3], a1, w3);
            }
            __syncthreads();  // buf (ci&1) free for reuse before next prefetch
        }

        // ---- activations: gates i,f,g,o -> c,h (all register-resident) ----
        float h0a, h0b, h1a, h1b;
        {
            float xi, xf, xg, xo, yi, yf, yg, yo;
            unpack2(xi, yi, acc[0][0]); unpack2(xf, yf, acc[0][1]);
            unpack2(xg, yg, acc[0][2]); unpack2(xo, yo, acc[0][3]);
            float ii = sigf(xi), ff = sigf(xf), gg = tanhf(xg), oo = sigf(xo);
            c0a = ff * c0a + ii * gg; h0a = oo * tanhf(c0a);
            ii = sigf(yi); ff = sigf(yf); gg = tanhf(yg); oo = sigf(yo);
            c0b = ff * c0b + ii * gg; h0b = oo * tanhf(c0b);

            unpack2(xi, yi, acc[1][0]); unpack2(xf, yf, acc[1][1]);
            unpack2(xg, yg, acc[1][2]); unpack2(xo, yo, acc[1][3]);
            ii = sigf(xi); ff = sigf(xf); gg = tanhf(xg); oo = sigf(xo);
            c1a = ff * c1a + ii * gg; h1a = oo * tanhf(c1a);
            ii = sigf(yi); ff = sigf(yf); gg = tanhf(yg); oo = sigf(yo);
            c1b = ff * c1b + ii * gg; h1b = oo * tanhf(c1b);
        }

        if (t < TT - 1) {
            float2* hd = (float2*)(g_hT[wb] + ghc * BB);
            hd[l]      = make_float2(h0a, h0b);   // batches 2l, 2l+1
            hd[l + 32] = make_float2(h1a, h1b);   // batches 2l+64, 2l+65
            grid_barrier(++gen);
        } else {
            out[(2 * l) * HH + ghc]            = h0a;
            out[(2 * l + 1) * HH + ghc]        = h0b;
            out[(2 * (l + 32)) * HH + ghc]     = h1a;
            out[(2 * (l + 32) + 1) * HH + ghc] = h1b;
        }
    }
}

extern "C" void kernel_launch(void* const* d_in, const int* in_sizes, int n_in,
                              void* d_out, int out_size) {
    const float* x    = (const float*)d_in[0];
    const float* W_ih = (const float*)d_in[1];
    const float* W_hh = (const float*)d_in[2];
    const float* b_ih = (const float*)d_in[3];
    const float* b_hh = (const float*)d_in[4];
    float* out = (float*)d_out;

    // 1) transpose x -> xT[t][i][b], reset barrier state (fresh each launch/replay)
    prep_kernel<<<dim3(II / 32, BB / 32, TT), dim3(32, 8)>>>(x);

    // 2) persistent fused LSTM (128 CTAs, 1/SM, 196 KB dynamic smem)
    const int smem_bytes = 16 * KTOT * 8 + 2 * KC * NPAIR * 8;  // 196608
    cudaFuncSetAttribute(lstm_kernel,
                         cudaFuncAttributeMaxDynamicSharedMemorySize, smem_bytes);
    lstm_kernel<<<GRID, NTHREADS, smem_bytes>>>(W_ih, W_hh, b_ih, b_hh, out);
}

// round 5
// speedup vs baseline: 1.1309x; 1.1309x over previous
#include <cuda_runtime.h>
#include <cstdint>
#include <math.h>

// Problem dims
#define BB   128
#define TT   1024
#define II   256
#define HH   512
#define G4H  2048      // 4*H gate rows

// Phase 2 config
#define P2_GRID    128 // CTAs; each owns 4 h-cols (16 gate rows)
#define P2_THREADS 256 // 8 warps = (hp 2) x (bh 2) x (kh 2)
#define KCH 32         // k per K-half per chunk
#define NCH 8          // chunks per step (256 / 32 per K-half)

// Phase 1 config
#define P1_THREADS 512
#define P1_KP      (II / 2)   // 128 k-pairs
#define XS_STRIDE  130        // ull per b-row (pad to kill bank conflicts)

typedef unsigned long long ull;

// Scratch (static __device__ arrays: allocation-free kernel_launch)
__device__ float g_xg[(size_t)TT * G4H * BB];  // [t][prow][b]  (1 GB) precomputed x-gates+bias
__device__ float g_hT[2][HH * BB];             // [buf][k][b]
__device__ unsigned g_bar_count;               // monotonic arrivals
__device__ unsigned g_bar_gen;                 // generation counter

// ---------- packed fp32 helpers ----------
__device__ __forceinline__ void fma2(ull &d, ull a, ull b) {
    asm("fma.rn.f32x2 %0, %1, %2, %0;" : "+l"(d) : "l"(a), "l"(b));
}
__device__ __forceinline__ void add2(ull &d, ull a) {
    asm("add.rn.f32x2 %0, %0, %1;" : "+l"(d) : "l"(a));
}
__device__ __forceinline__ ull pack2(float lo, float hi) {
    ull r; asm("mov.b64 %0, {%1, %2};" : "=l"(r) : "f"(lo), "f"(hi)); return r;
}
__device__ __forceinline__ void unpack2(float &lo, float &hi, ull v) {
    asm("mov.b64 {%0, %1}, %2;" : "=f"(lo), "=f"(hi) : "l"(v));
}
// ---------- cp.async ----------
__device__ __forceinline__ void cp_async16(void* dst_smem, const void* src) {
    unsigned d = (unsigned)__cvta_generic_to_shared(dst_smem);
    asm volatile("cp.async.cg.shared.global [%0], [%1], 16;" :: "r"(d), "l"(src));
}
__device__ __forceinline__ void cp_commit() { asm volatile("cp.async.commit_group;"); }
template<int N> __device__ __forceinline__ void cp_wait() {
    asm volatile("cp.async.wait_group %0;" :: "n"(N));
}

__device__ __forceinline__ float sigf(float x) { return 1.0f / (1.0f + expf(-x)); }

// prow (phase-2-local gate row ordering) -> global gate row n
__device__ __forceinline__ int prow_to_n(int prow) {
    int c2 = prow >> 4, r = prow & 15;
    return (r & 3) * HH + c2 * 4 + (r >> 2);   // n = gate*512 + cta*4 + hc
}

// ---------- grid-wide barrier (monotonic count: no reset race) ----------
__device__ __forceinline__ void grid_barrier(unsigned target) {
    __syncthreads();
    __threadfence();
    if (threadIdx.x == 0) {
        unsigned a = atomicAdd(&g_bar_count, 1u) + 1u;
        if (a == (unsigned)P2_GRID * target) {
            __threadfence();
            atomicAdd(&g_bar_gen, 1u);
        } else {
            while (*(volatile unsigned*)&g_bar_gen < target) { }
        }
        __threadfence();
    }
    __syncthreads();
}

// ============================================================================
// Phase 1: xg[t][prow][b] = sum_i x[b][t][i]*W_ih[n(prow)][i] + b_ih[n] + b_hh[n]
// K-pair packing: f32x2 lanes hold even/odd k; final = lo+hi. grid (16, 1024).
// ============================================================================
__global__ void __launch_bounds__(P1_THREADS, 1) xgate_kernel(
    const float* __restrict__ x, const float* __restrict__ W_ih,
    const float* __restrict__ b_ih, const float* __restrict__ b_hh)
{
    extern __shared__ char smem[];
    ull*   xs2   = (ull*)smem;     // [128 b][XS_STRIDE kp] (k-pair packed x_t)
    float* s_out = (float*)smem;   // reused after compute: [128 row][129]

    const int tid = threadIdx.x;
    const int gy  = blockIdx.x;    // 0..15: prow group of 128
    const int t   = blockIdx.y;    // 0..1023

    if (gy == 0 && t == 0 && tid == 0) { g_bar_count = 0u; g_bar_gen = 0u; }

    // Stage x_t transposed+packed: xs2[b][kp] = (x[b][t][2kp], x[b][t][2kp+1])
    for (int e = tid; e < BB * (II / 4); e += P1_THREADS) {  // 8192 float4s
        int b = e >> 6, v = e & 63;
        float4 f = *(const float4*)(x + ((size_t)b * TT + t) * II + 4 * v);
        ulonglong2 u;
        u.x = pack2(f.x, f.y);
        u.y = pack2(f.z, f.w);
        *(ulonglong2*)&xs2[b * XS_STRIDE + 2 * v] = u;       // STS.128, conflict-free
    }
    __syncthreads();

    const int rs   = tid >> 3;           // 0..63 rowslot (2 prows each)
    const int boct = tid & 7;            // 0..7  -> b = boct + 8*bb
    const int p0   = gy * 128 + rs * 2;
    const int n0 = prow_to_n(p0), n1 = prow_to_n(p0 + 1);
    const ull* W0 = (const ull*)(W_ih + n0 * II);   // k-pairs contiguous
    const ull* W1 = (const ull*)(W_ih + n1 * II);
    const float bias0 = b_ih[n0] + b_hh[n0];
    const float bias1 = b_ih[n1] + b_hh[n1];

    ull acc0[16], acc1[16];
    #pragma unroll
    for (int bb = 0; bb < 16; bb++) {
        acc0[bb] = pack2(bias0, 0.f);
        acc1[bb] = pack2(bias1, 0.f);
    }

    #pragma unroll 2
    for (int kp = 0; kp < P1_KP; kp++) {
        ull w0 = __ldg(W0 + kp);
        ull w1 = __ldg(W1 + kp);
        #pragma unroll
        for (int bb = 0; bb < 16; bb++) {
            ull a = xs2[(boct + 8 * bb) * XS_STRIDE + kp];   // broadcast, conflict-free
            fma2(acc0[bb], a, w0);
            fma2(acc1[bb], a, w1);
        }
    }
    __syncthreads();  // all xs2 reads done before s_out overwrite

    #pragma unroll
    for (int bb = 0; bb < 16; bb++) {
        float lo, hi;
        unpack2(lo, hi, acc0[bb]);
        s_out[(rs * 2 + 0) * 129 + boct + 8 * bb] = lo + hi;
        unpack2(lo, hi, acc1[bb]);
        s_out[(rs * 2 + 1) * 129 + boct + 8 * bb] = lo + hi;
    }
    __syncthreads();

    float* dst = g_xg + ((size_t)t * G4H + gy * 128) * BB;
    for (int e = tid; e < 128 * 128; e += P1_THREADS) {
        int row = e >> 7, b = e & 127;
        dst[e] = s_out[row * 129 + b];   // coalesced STG
    }
}

// ---------- phase-2 activation chunk loader ----------
// As[buf][kh][kk][64 pairs]; chunk ci = k in {kh*256 + ci*32 + kk}
__device__ __forceinline__ void load_chunk2(ull* As, int ci,
                                            const float* __restrict__ hsrc, int tid) {
    ull* dst = As + (ci & 1) * (2 * KCH * 64);
    #pragma unroll
    for (int j = 0; j < 8; j++) {
        int e   = tid + j * P2_THREADS;   // 0..2047 16B-units
        int khh = e >> 10;
        int rem = e & 1023;
        int kk  = rem >> 5, pu = rem & 31;
        const float* src = hsrc + (khh * 256 + ci * KCH + kk) * BB + pu * 4;
        cp_async16(dst + (khh * KCH + kk) * 64 + pu * 2, src);
    }
}

// ============================================================================
// Phase 2: persistent recurrence. 128 CTAs x 256 threads.
// warp = (hp: h-col pair, bh: batch half, kh: K half). K-split reduced via smem.
// ============================================================================
__global__ void __launch_bounds__(P2_THREADS, 1) lstm_kernel(
    const float* __restrict__ W_hh, float* __restrict__ out)
{
    extern __shared__ char smem[];
    ull* wsm = (ull*)smem;               // [512 k][16 rows] dup-packed  (64 KB)
    ull* As  = wsm + HH * 16;            // [2 buf][2 kh][32 kk][64 p]   (64 KB)
    ull* xgs = As + 2 * 2 * KCH * 64;    // [2 tbuf][16 r][64 p]         (16 KB)
    ull* red = xgs + 2 * 16 * 64;        // [4 warp'][8 j][32 l]         ( 8 KB)

    const int tid = threadIdx.x;
    const int w = tid >> 5, l = tid & 31;
    const int kh = w & 1, bh = (w >> 1) & 1, hp = (w >> 2) & 1;
    const int cta = blockIdx.x;
    const int p = bh * 32 + l;           // batch pair 0..63 -> batches 2p, 2p+1

    // Weights once: wsm[k][r], r = hc*4+g, n = g*512 + cta*4 + hc, dup-packed
    for (int idx = tid; idx < HH * 16; idx += P2_THREADS) {
        int k = idx >> 4, r = idx & 15;
        int n = (r & 3) * HH + cta * 4 + (r >> 2);
        float v = W_hh[n * HH + k];
        wsm[idx] = pack2(v, v);
    }
    // Zero h buf0 slice (4 h-cols x 128 b)
    for (int e = tid; e < 512; e += P2_THREADS)
        g_hT[0][(cta * 4 + (e >> 7)) * BB + (e & 127)] = 0.f;

    // Prefetch xg(t=0) into xgs[0]
    {
        const float* src = g_xg + ((size_t)cta * 16) * BB;
        for (int e = tid; e < 512; e += P2_THREADS)
            cp_async16((char*)xgs + e * 16, src + e * 4);
        cp_commit();
    }

    float c_lo[2] = {0.f, 0.f}, c_hi[2] = {0.f, 0.f};  // cell state (kh0 lanes)

    unsigned gen = 0;
    grid_barrier(++gen);   // h buf0 zeroed everywhere (also covers xg prefetch ordering)

    for (int t = 0; t < TT; t++) {
        const float* hsrc = g_hT[t & 1];
        ull* xg_cur = xgs + (t & 1) * 1024;

        load_chunk2(As, 0, hsrc, tid); cp_commit();   // C0
        load_chunk2(As, 1, hsrc, tid); cp_commit();   // C1
        if (t + 1 < TT) {                             // Cxg: next step's xg (DRAM)
            const float* src = g_xg + ((size_t)(t + 1) * G4H + cta * 16) * BB;
            ull* xdst = xgs + ((t + 1) & 1) * 1024;
            for (int e = tid; e < 512; e += P2_THREADS)
                cp_async16((char*)xdst + e * 16, src + e * 4);
            cp_commit();
        } else {
            cp_commit();   // empty group keeps accounting uniform
        }
        cp_wait<2>();      // C0 done (C1, Cxg may be pending)
        __syncthreads();

        ull acc[8];
        if (kh == 0) {     // init with precomputed x-gates (+bias already folded)
            #pragma unroll
            for (int j = 0; j < 8; j++)
                acc[j] = xg_cur[(hp * 8 + j) * 64 + p];
        } else {
            #pragma unroll
            for (int j = 0; j < 8; j++) acc[j] = 0ull;
        }

        #pragma unroll
        for (int ci = 0; ci < NCH; ci++) {
            const ull* Ab = As + ((ci & 1) * 2 + kh) * (KCH * 64);
            const int kbase = (kh * 256 + ci * KCH) * 16 + hp * 8;
            #pragma unroll 8
            for (int kk = 0; kk < KCH; kk++) {
                ull a = Ab[kk * 64 + p];
                const ull* wr = wsm + kbase + kk * 16;
                ulonglong2 w01 = *(const ulonglong2*)(wr);
                ulonglong2 w23 = *(const ulonglong2*)(wr + 2);
                ulonglong2 w45 = *(const ulonglong2*)(wr + 4);
                ulonglong2 w67 = *(const ulonglong2*)(wr + 6);
                fma2(acc[0], a, w01.x); fma2(acc[1], a, w01.y);
                fma2(acc[2], a, w23.x); fma2(acc[3], a, w23.y);
                fma2(acc[4], a, w45.x); fma2(acc[5], a, w45.y);
                fma2(acc[6], a, w67.x); fma2(acc[7], a, w67.y);
            }
            if (ci < NCH - 1) {
                __syncthreads();                       // buf (ci&1) fully consumed
                if (ci < NCH - 2) {
                    load_chunk2(As, ci + 2, hsrc, tid);
                    cp_commit();
                    cp_wait<1>();                      // chunk ci+1 ready
                } else {
                    cp_wait<0>();                      // last chunk ready
                }
                __syncthreads();
            }
        }

        // ---- K-half reduction (kh1 -> kh0) ----
        if (kh == 1) {
            ull* rb = red + ((hp * 2 + bh) * 8) * 32;
            #pragma unroll
            for (int j = 0; j < 8; j++) rb[j * 32 + l] = acc[j];
        }
        __syncthreads();
        if (kh == 0) {
            const ull* rb = red + ((hp * 2 + bh) * 8) * 32;
            #pragma unroll
            for (int j = 0; j < 8; j++) add2(acc[j], rb[j * 32 + l]);

            // ---- activations: 2 h-cols x 2 batches, c register-resident ----
            #pragma unroll
            for (int h2 = 0; h2 < 2; h2++) {
                float xi, yi, xf, yf, xg_, yg_, xo, yo;
                unpack2(xi, yi, acc[h2 * 4 + 0]);
                unpack2(xf, yf, acc[h2 * 4 + 1]);
                unpack2(xg_, yg_, acc[h2 * 4 + 2]);
                unpack2(xo, yo, acc[h2 * 4 + 3]);
                float ig = sigf(xi), fg = sigf(xf), gg = tanhf(xg_), og = sigf(xo);
                c_lo[h2] = fg * c_lo[h2] + ig * gg;
                float hlo = og * tanhf(c_lo[h2]);
                ig = sigf(yi); fg = sigf(yf); gg = tanhf(yg_); og = sigf(yo);
                c_hi[h2] = fg * c_hi[h2] + ig * gg;
                float hhi = og * tanhf(c_hi[h2]);

                int ghc = cta * 4 + hp * 2 + h2;
                if (t < TT - 1) {
                    *(float2*)&g_hT[(t + 1) & 1][ghc * BB + 2 * p] =
                        make_float2(hlo, hhi);
                } else {
                    out[(2 * p) * HH + ghc]     = hlo;
                    out[(2 * p + 1) * HH + ghc] = hhi;
                }
            }
        }
        if (t < TT - 1) grid_barrier(++gen);
    }
}

extern "C" void kernel_launch(void* const* d_in, const int* in_sizes, int n_in,
                              void* d_out, int out_size) {
    const float* x    = (const float*)d_in[0];
    const float* W_ih = (const float*)d_in[1];
    const float* W_hh = (const float*)d_in[2];
    const float* b_ih = (const float*)d_in[3];
    const float* b_hh = (const float*)d_in[4];
    float* out = (float*)d_out;

    const int p1_smem = BB * XS_STRIDE * 8;                         // 133,120 B
    const int p2_smem = (HH * 16 + 2 * 2 * KCH * 64 + 2 * 16 * 64 + 4 * 8 * 32) * 8; // 155,648 B
    cudaFuncSetAttribute(xgate_kernel,
                         cudaFuncAttributeMaxDynamicSharedMemorySize, p1_smem);
    cudaFuncSetAttribute(lstm_kernel,
                         cudaFuncAttributeMaxDynamicSharedMemorySize, p2_smem);

    // Phase 1: all-timestep x-gate projection (also resets barrier state)
    xgate_kernel<<<dim3(16, TT), P1_THREADS, p1_smem>>>(x, W_ih, b_ih, b_hh);
    // Phase 2: persistent recurrence, K=512
    lstm_kernel<<<P2_GRID, P2_THREADS, p2_smem>>>(W_hh, out);
}

// round 6
// speedup vs baseline: 1.2980x; 1.1477x over previous
#include <cuda_runtime.h>
#include <cstdint>
#include <math.h>

// Problem dims
#define BB   128
#define TT   1024
#define II   256
#define HH   512
#define G4H  2048

// Phase 2 config
#define P2_GRID    128
#define P2_THREADS 256
#define KCH  32        // k per K-half per chunk
#define NCH  8         // chunks per step (8 * 64 global k = 512)
#define NBUF 4

// Phase 1 config
#define P1_THREADS 512
#define P1_KP      (II / 2)
#define XS_STRIDE  130

typedef unsigned long long ull;

__device__ float g_xg[(size_t)TT * G4H * BB];  // [t][prow][b] precomputed x-gates+bias
__device__ float g_hT[2][HH * BB];             // [buf][k][b]
__device__ unsigned g_bar_count;
__device__ unsigned g_bar_gen;

// ---------- packed fp32 helpers ----------
__device__ __forceinline__ void fma2(ull &d, ull a, ull b) {
    asm("fma.rn.f32x2 %0, %1, %2, %0;" : "+l"(d) : "l"(a), "l"(b));
}
__device__ __forceinline__ void add2(ull &d, ull a) {
    asm("add.rn.f32x2 %0, %0, %1;" : "+l"(d) : "l"(a));
}
__device__ __forceinline__ ull pack2(float lo, float hi) {
    ull r; asm("mov.b64 %0, {%1, %2};" : "=l"(r) : "f"(lo), "f"(hi)); return r;
}
__device__ __forceinline__ void unpack2(float &lo, float &hi, ull v) {
    asm("mov.b64 {%0, %1}, %2;" : "=f"(lo), "=f"(hi) : "l"(v));
}
// ---------- cp.async ----------
__device__ __forceinline__ void cp_async16(void* dst_smem, const void* src) {
    unsigned d = (unsigned)__cvta_generic_to_shared(dst_smem);
    asm volatile("cp.async.cg.shared.global [%0], [%1], 16;" :: "r"(d), "l"(src));
}
__device__ __forceinline__ void cp_commit() { asm volatile("cp.async.commit_group;"); }
template<int N> __device__ __forceinline__ void cp_wait() {
    asm volatile("cp.async.wait_group %0;" :: "n"(N));
}

__device__ __forceinline__ float sigf(float x) { return 1.0f / (1.0f + expf(-x)); }

__device__ __forceinline__ int prow_to_n(int prow) {
    int c2 = prow >> 4, r = prow & 15;
    return (r & 3) * HH + c2 * 4 + (r >> 2);
}

// ---------- grid-wide barrier (monotonic count) ----------
__device__ __forceinline__ void grid_barrier(unsigned target) {
    __syncthreads();
    __threadfence();
    if (threadIdx.x == 0) {
        unsigned a = atomicAdd(&g_bar_count, 1u) + 1u;
        if (a == (unsigned)P2_GRID * target) {
            __threadfence();
            atomicAdd(&g_bar_gen, 1u);
        } else {
            while (*(volatile unsigned*)&g_bar_gen < target) { }
        }
        __threadfence();
    }
    __syncthreads();
}

// ============================================================================
// Phase 1 (unchanged from R5): xg[t][prow][b] = x.W_ih^T + b_ih + b_hh
// ============================================================================
__global__ void __launch_bounds__(P1_THREADS, 1) xgate_kernel(
    const float* __restrict__ x, const float* __restrict__ W_ih,
    const float* __restrict__ b_ih, const float* __restrict__ b_hh)
{
    extern __shared__ char smem[];
    ull*   xs2   = (ull*)smem;
    float* s_out = (float*)smem;

    const int tid = threadIdx.x;
    const int gy  = blockIdx.x;
    const int t   = blockIdx.y;

    if (gy == 0 && t == 0 && tid == 0) { g_bar_count = 0u; g_bar_gen = 0u; }

    for (int e = tid; e < BB * (II / 4); e += P1_THREADS) {
        int b = e >> 6, v = e & 63;
        float4 f = *(const float4*)(x + ((size_t)b * TT + t) * II + 4 * v);
        ulonglong2 u;
        u.x = pack2(f.x, f.y);
        u.y = pack2(f.z, f.w);
        *(ulonglong2*)&xs2[b * XS_STRIDE + 2 * v] = u;
    }
    __syncthreads();

    const int rs   = tid >> 3;
    const int boct = tid & 7;
    const int p0   = gy * 128 + rs * 2;
    const int n0 = prow_to_n(p0), n1 = prow_to_n(p0 + 1);
    const ull* W0 = (const ull*)(W_ih + n0 * II);
    const ull* W1 = (const ull*)(W_ih + n1 * II);
    const float bias0 = b_ih[n0] + b_hh[n0];
    const float bias1 = b_ih[n1] + b_hh[n1];

    ull acc0[16], acc1[16];
    #pragma unroll
    for (int bb = 0; bb < 16; bb++) {
        acc0[bb] = pack2(bias0, 0.f);
        acc1[bb] = pack2(bias1, 0.f);
    }

    #pragma unroll 2
    for (int kp = 0; kp < P1_KP; kp++) {
        ull w0 = __ldg(W0 + kp);
        ull w1 = __ldg(W1 + kp);
        #pragma unroll
        for (int bb = 0; bb < 16; bb++) {
            ull a = xs2[(boct + 8 * bb) * XS_STRIDE + kp];
            fma2(acc0[bb], a, w0);
            fma2(acc1[bb], a, w1);
        }
    }
    __syncthreads();

    #pragma unroll
    for (int bb = 0; bb < 16; bb++) {
        float lo, hi;
        unpack2(lo, hi, acc0[bb]);
        s_out[(rs * 2 + 0) * 129 + boct + 8 * bb] = lo + hi;
        unpack2(lo, hi, acc1[bb]);
        s_out[(rs * 2 + 1) * 129 + boct + 8 * bb] = lo + hi;
    }
    __syncthreads();

    float* dst = g_xg + ((size_t)t * G4H + gy * 128) * BB;
    for (int e = tid; e < 128 * 128; e += P1_THREADS) {
        int row = e >> 7, b = e & 127;
        dst[e] = s_out[row * 129 + b];
    }
}

// ---------- phase-2 chunk loader: As[ci&3][kh][kk][64 pairs] ----------
__device__ __forceinline__ void load_chunk(ull* As, int ci,
                                           const float* __restrict__ hsrc, int tid) {
    ull* dst = As + (ci & 3) * (2 * KCH * 64);
    #pragma unroll
    for (int j = 0; j < 8; j++) {
        int e   = tid + j * P2_THREADS;   // 0..2047 16B-units
        int khh = e >> 10;
        int rem = e & 1023;
        int kk  = rem >> 5, pu = rem & 31;
        const float* src = hsrc + (khh * 256 + ci * KCH + kk) * BB + pu * 4;
        cp_async16(dst + (khh * KCH + kk) * 64 + pu * 2, src);
    }
}

// ============================================================================
// Phase 2: persistent recurrence. warp=(kh,wq), lane=(hc,sub).
// Thread: 2 pairs (4 batches) x 1 h-col x 4 gates over its K-half.
// 4-buffer cp.async ring, issue-distance 2, ONE __syncthreads per chunk.
// ============================================================================
__global__ void __launch_bounds__(P2_THREADS, 1) lstm_kernel(
    const float* __restrict__ W_hh, float* __restrict__ out)
{
    extern __shared__ char smem[];
    ull* wsm = (ull*)smem;                  // [512 k][16 r] dup-packed   64 KB
    ull* As  = wsm + HH * 16;               // [4 buf][2 kh][32 kk][64 p] 128 KB
    ull* xgs = As + NBUF * 2 * KCH * 64;    // [2 tbuf][16 r][64 p]       16 KB
    ull* red = xgs + 2 * 16 * 64;           // [2 kh][128 t][4 g]          8 KB

    const int tid  = threadIdx.x;
    const int w    = tid >> 5, l = tid & 31;
    const int kh   = w >> 2;             // K half
    const int wq   = w & 3;
    const int hc   = l >> 3;             // local h-col 0..3
    const int pd   = wq * 8 + (l & 7);   // pair-duo 0..31 (pairs 2pd, 2pd+1)
    const int t128 = wq * 32 + l;        // 0..127 within kh group
    const int cta  = blockIdx.x;
    const int ghc  = cta * 4 + hc;
    const int myp  = 2 * pd + kh;        // owned pair after exchange

    // Weights once: wsm[k][r], r = hc*4+g, n = g*512 + cta*4 + hc
    for (int idx = tid; idx < HH * 16; idx += P2_THREADS) {
        int k = idx >> 4, r = idx & 15;
        int n = (r & 3) * HH + cta * 4 + (r >> 2);
        float v = W_hh[n * HH + k];
        wsm[idx] = pack2(v, v);
    }
    // Zero h buf0 slice
    for (int e = tid; e < 512; e += P2_THREADS)
        g_hT[0][(cta * 4 + (e >> 7)) * BB + (e & 127)] = 0.f;
    // Prefetch xg(0)
    {
        const float* src = g_xg + ((size_t)cta * 16) * BB;
        for (int e = tid; e < 512; e += P2_THREADS)
            cp_async16((char*)xgs + e * 16, src + e * 4);
        cp_commit();
    }

    float cA = 0.f, cB = 0.f;   // cell state for batches 2*myp, 2*myp+1
    unsigned gen = 0;
    grid_barrier(++gen);

    for (int t = 0; t < TT; t++) {
        const float* hsrc = g_hT[t & 1];
        const ull* xg_cur = xgs + (t & 1) * 1024;

        load_chunk(As, 0, hsrc, tid); cp_commit();
        load_chunk(As, 1, hsrc, tid); cp_commit();

        ull accA[4], accB[4];

        #pragma unroll 1
        for (int ci = 0; ci < NCH; ci++) {
            if (ci < NCH - 2) {
                load_chunk(As, ci + 2, hsrc, tid);
                cp_commit();
            } else if (ci == NCH - 2) {
                if (t + 1 < TT) {   // prefetch next step's xg (own slot, DRAM)
                    const float* src = g_xg + ((size_t)(t + 1) * G4H + cta * 16) * BB;
                    char* xdst = (char*)xgs + ((t + 1) & 1) * 8192;
                    for (int e = tid; e < 512; e += P2_THREADS)
                        cp_async16(xdst + e * 16, src + e * 4);
                }
                cp_commit();        // (possibly empty) keeps group accounting uniform
            }
            if (ci == NCH - 1) cp_wait<1>(); else cp_wait<2>();
            __syncthreads();        // chunk ci (and, at ci==0, xg(t)) visible to all

            if (ci == 0) {
                if (kh == 0) {
                    #pragma unroll
                    for (int g = 0; g < 4; g++) {
                        ulonglong2 xg2 =
                            *(const ulonglong2*)&xg_cur[(hc * 4 + g) * 64 + 2 * pd];
                        accA[g] = xg2.x; accB[g] = xg2.y;
                    }
                } else {
                    #pragma unroll
                    for (int g = 0; g < 4; g++) { accA[g] = 0ull; accB[g] = 0ull; }
                }
            }

            const ull* Ab = As + (ci & 3) * (2 * KCH * 64) + kh * (KCH * 64);
            const ull* Wk = wsm + (kh * 256 + ci * KCH) * 16 + hc * 4;
            #pragma unroll
            for (int kk = 0; kk < KCH; kk++) {
                ulonglong2 a2  = *(const ulonglong2*)&Ab[kk * 64 + 2 * pd];
                ulonglong2 w01 = *(const ulonglong2*)(Wk + kk * 16);
                ulonglong2 w23 = *(const ulonglong2*)(Wk + kk * 16 + 2);
                fma2(accA[0], a2.x, w01.x); fma2(accB[0], a2.y, w01.x);
                fma2(accA[1], a2.x, w01.y); fma2(accB[1], a2.y, w01.y);
                fma2(accA[2], a2.x, w23.x); fma2(accB[2], a2.y, w23.x);
                fma2(accA[3], a2.x, w23.y); fma2(accB[3], a2.y, w23.y);
            }
        }

        // ---- symmetric kh exchange: send non-owned pair's partials ----
        {
            ull* slot = red + (kh * 128 + t128) * 4;
            ulonglong2 s01, s23;
            if (kh == 0) { s01.x = accB[0]; s01.y = accB[1]; s23.x = accB[2]; s23.y = accB[3]; }
            else         { s01.x = accA[0]; s01.y = accA[1]; s23.x = accA[2]; s23.y = accA[3]; }
            *(ulonglong2*)slot       = s01;
            *(ulonglong2*)(slot + 2) = s23;
        }
        __syncthreads();
        ull mine[4];
        {
            const ull* rslot = red + ((kh ^ 1) * 128 + t128) * 4;
            ulonglong2 o01 = *(const ulonglong2*)rslot;
            ulonglong2 o23 = *(const ulonglong2*)(rslot + 2);
            mine[0] = (kh == 0) ? accA[0] : accB[0];  add2(mine[0], o01.x);
            mine[1] = (kh == 0) ? accA[1] : accB[1];  add2(mine[1], o01.y);
            mine[2] = (kh == 0) ? accA[2] : accB[2];  add2(mine[2], o23.x);
            mine[3] = (kh == 0) ? accA[3] : accB[3];  add2(mine[3], o23.y);
        }

        // ---- activations (all 256 threads; 2 batches each) ----
        float xi, yi, xf, yf, xg_, yg_, xo, yo;
        unpack2(xi, yi, mine[0]); unpack2(xf, yf, mine[1]);
        unpack2(xg_, yg_, mine[2]); unpack2(xo, yo, mine[3]);
        float ig = sigf(xi), fg = sigf(xf), gg = tanhf(xg_), og = sigf(xo);
        cA = fg * cA + ig * gg;  float hlo = og * tanhf(cA);
        ig = sigf(yi); fg = sigf(yf); gg = tanhf(yg_); og = sigf(yo);
        cB = fg * cB + ig * gg;  float hhi = og * tanhf(cB);

        if (t < TT - 1) {
            *(float2*)&g_hT[(t + 1) & 1][ghc * BB + 2 * myp] = make_float2(hlo, hhi);
            grid_barrier(++gen);
        } else {
            out[(2 * myp) * HH + ghc]     = hlo;
            out[(2 * myp + 1) * HH + ghc] = hhi;
        }
    }
}

extern "C" void kernel_launch(void* const* d_in, const int* in_sizes, int n_in,
                              void* d_out, int out_size) {
    const float* x    = (const float*)d_in[0];
    const float* W_ih = (const float*)d_in[1];
    const float* W_hh = (const float*)d_in[2];
    const float* b_ih = (const float*)d_in[3];
    const float* b_hh = (const float*)d_in[4];
    float* out = (float*)d_out;

    const int p1_smem = BB * XS_STRIDE * 8;                                   // 133,120
    const int p2_smem = (HH * 16 + NBUF * 2 * KCH * 64 + 2 * 16 * 64
                         + 2 * 128 * 4) * 8;                                  // 221,184
    cudaFuncSetAttribute(xgate_kernel,
                         cudaFuncAttributeMaxDynamicSharedMemorySize, p1_smem);
    cudaFuncSetAttribute(lstm_kernel,
                         cudaFuncAttributeMaxDynamicSharedMemorySize, p2_smem);

    xgate_kernel<<<dim3(16, TT), P1_THREADS, p1_smem>>>(x, W_ih, b_ih, b_hh);
    lstm_kernel<<<P2_GRID, P2_THREADS, p2_smem>>>(W_hh, out);
}

// round 7
// speedup vs baseline: 1.3008x; 1.0022x over previous
#include <cuda_runtime.h>
#include <cstdint>
#include <math.h>

// Problem dims
#define BB   128
#define TT   1024
#define II   256
#define HH   512
#define G4H  2048

// Phase 2 config
#define P2_GRID    128
#define P2_THREADS 256
#define KPT  256       // total k-pairs (512 k)
#define KPC  32        // k-pairs per chunk
#define NCH  8
#define NBUF 4
#define AST  130       // activation row stride (ull) — 1040 B, staggers banks
#define WST  18        // weight row stride (ull) — 144 B, staggers banks

// Phase 1 config
#define P1_THREADS 512
#define P1_KP      (II / 2)
#define XS_STRIDE  130

typedef unsigned long long ull;

__device__ float g_xg[(size_t)TT * G4H * BB];  // [t][prow][b] x-gates + biases
__device__ ull   g_hT_pk[2][KPT * BB];         // [buf][kp][b] h k-pair packed
__device__ unsigned g_bar_count;
__device__ unsigned g_bar_gen;

// ---------- packed fp32 helpers ----------
__device__ __forceinline__ void fma2(ull &d, ull a, ull b) {
    asm("fma.rn.f32x2 %0, %1, %2, %0;" : "+l"(d) : "l"(a), "l"(b));
}
__device__ __forceinline__ ull pack2(float lo, float hi) {
    ull r; asm("mov.b64 %0, {%1, %2};" : "=l"(r) : "f"(lo), "f"(hi)); return r;
}
__device__ __forceinline__ void unpack2(float &lo, float &hi, ull v) {
    asm("mov.b64 {%0, %1}, %2;" : "=f"(lo), "=f"(hi) : "l"(v));
}
// ---------- cp.async ----------
__device__ __forceinline__ void cp_async16(void* dst_smem, const void* src) {
    unsigned d = (unsigned)__cvta_generic_to_shared(dst_smem);
    asm volatile("cp.async.cg.shared.global [%0], [%1], 16;" :: "r"(d), "l"(src));
}
__device__ __forceinline__ void cp_commit() { asm volatile("cp.async.commit_group;"); }
template<int N> __device__ __forceinline__ void cp_wait() {
    asm volatile("cp.async.wait_group %0;" :: "n"(N));
}

__device__ __forceinline__ float sigf(float x) { return 1.0f / (1.0f + expf(-x)); }

__device__ __forceinline__ int prow_to_n(int prow) {
    int c2 = prow >> 4, r = prow & 15;
    return (r & 3) * HH + c2 * 4 + (r >> 2);
}

// ---------- grid-wide barrier (monotonic count) ----------
__device__ __forceinline__ void grid_barrier(unsigned target) {
    __syncthreads();
    __threadfence();
    if (threadIdx.x == 0) {
        unsigned a = atomicAdd(&g_bar_count, 1u) + 1u;
        if (a == (unsigned)P2_GRID * target) {
            __threadfence();
            atomicAdd(&g_bar_gen, 1u);
        } else {
            while (*(volatile unsigned*)&g_bar_gen < target) { }
        }
        __threadfence();
    }
    __syncthreads();
}

// ============================================================================
// Phase 1 (unchanged): xg[t][prow][b] = x.W_ih^T + b_ih + b_hh
// ============================================================================
__global__ void __launch_bounds__(P1_THREADS, 1) xgate_kernel(
    const float* __restrict__ x, const float* __restrict__ W_ih,
    const float* __restrict__ b_ih, const float* __restrict__ b_hh)
{
    extern __shared__ char smem[];
    ull*   xs2   = (ull*)smem;
    float* s_out = (float*)smem;

    const int tid = threadIdx.x;
    const int gy  = blockIdx.x;
    const int t   = blockIdx.y;

    if (gy == 0 && t == 0 && tid == 0) { g_bar_count = 0u; g_bar_gen = 0u; }

    for (int e = tid; e < BB * (II / 4); e += P1_THREADS) {
        int b = e >> 6, v = e & 63;
        float4 f = *(const float4*)(x + ((size_t)b * TT + t) * II + 4 * v);
        ulonglong2 u;
        u.x = pack2(f.x, f.y);
        u.y = pack2(f.z, f.w);
        *(ulonglong2*)&xs2[b * XS_STRIDE + 2 * v] = u;
    }
    __syncthreads();

    const int rs   = tid >> 3;
    const int boct = tid & 7;
    const int p0   = gy * 128 + rs * 2;
    const int n0 = prow_to_n(p0), n1 = prow_to_n(p0 + 1);
    const ull* W0 = (const ull*)(W_ih + n0 * II);
    const ull* W1 = (const ull*)(W_ih + n1 * II);
    const float bias0 = b_ih[n0] + b_hh[n0];
    const float bias1 = b_ih[n1] + b_hh[n1];

    ull acc0[16], acc1[16];
    #pragma unroll
    for (int bb = 0; bb < 16; bb++) {
        acc0[bb] = pack2(bias0, 0.f);
        acc1[bb] = pack2(bias1, 0.f);
    }

    #pragma unroll 2
    for (int kp = 0; kp < P1_KP; kp++) {
        ull w0 = __ldg(W0 + kp);
        ull w1 = __ldg(W1 + kp);
        #pragma unroll
        for (int bb = 0; bb < 16; bb++) {
            ull a = xs2[(boct + 8 * bb) * XS_STRIDE + kp];
            fma2(acc0[bb], a, w0);
            fma2(acc1[bb], a, w1);
        }
    }
    __syncthreads();

    #pragma unroll
    for (int bb = 0; bb < 16; bb++) {
        float lo, hi;
        unpack2(lo, hi, acc0[bb]);
        s_out[(rs * 2 + 0) * 129 + boct + 8 * bb] = lo + hi;
        unpack2(lo, hi, acc1[bb]);
        s_out[(rs * 2 + 1) * 129 + boct + 8 * bb] = lo + hi;
    }
    __syncthreads();

    float* dst = g_xg + ((size_t)t * G4H + gy * 128) * BB;
    for (int e = tid; e < 128 * 128; e += P1_THREADS) {
        int row = e >> 7, b = e & 127;
        dst[e] = s_out[row * 129 + b];
    }
}

// ---------- phase-2 chunk loader: As[ci&3][kpl][b] (padded rows) ----------
__device__ __forceinline__ void load_chunk(ull* As, int ci,
                                           const ull* __restrict__ hsrc, int tid) {
    ull* dst = As + (ci & 3) * (KPC * AST);
    const ull* src = hsrc + ci * KPC * BB;
    #pragma unroll
    for (int j = 0; j < 8; j++) {
        int u   = tid + j * P2_THREADS;   // 0..2047 16B units
        int kpl = u >> 6;
        int bu  = u & 63;
        cp_async16(dst + kpl * AST + bu * 2, src + kpl * BB + bu * 2);
    }
}

// ============================================================================
// Phase 2: persistent recurrence. 8x8 register tile, k-pair f32x2 packing.
// lane: kps = l&7 (kp-slice), rg = (l>>3)&1 (row group), bglow = l>>4.
// bg = warp*2 + bglow. Thread: rows rg*8..+7, batches bg*8..+7, kp = j*8+kps.
// ============================================================================
__global__ void __launch_bounds__(P2_THREADS, 1) lstm_kernel(
    const float* __restrict__ W_hh, float* __restrict__ out)
{
    extern __shared__ char smem[];
    ull*   wsm = (ull*)smem;                    // [256 kp][18] (16 used)  36,864 B
    ull*   As  = wsm + KPT * WST;               // [4][32][130]           133,120 B
    float* xgs = (float*)(As + NBUF * KPC * AST); // [2][16][128]          16,384 B

    const int tid = threadIdx.x;
    const int w   = tid >> 5, l = tid & 31;
    const int kps = l & 7;
    const int rg  = (l >> 3) & 1;
    const int bg  = w * 2 + (l >> 4);
    const int cta = blockIdx.x;
    const int b   = bg * 8 + kps;      // owned batch after reduction
    const int kpg = cta * 2 + rg;      // owned h k-pair row (h-cols 2kpg, 2kpg+1)

    // Weights once: wsm[kp*WST + r] = (W_hh[n][2kp], W_hh[n][2kp+1]) — no dup
    for (int idx = tid; idx < KPT * 16; idx += P2_THREADS) {
        int kp = idx >> 4, r = idx & 15;
        int n = (r & 3) * HH + cta * 4 + (r >> 2);
        wsm[kp * WST + r] = ((const ull*)W_hh)[n * (HH / 2) + kp];
    }
    // Zero h buf0 own rows (2 kp rows x 128 b)
    g_hT_pk[0][(cta * 2 + (tid >> 7)) * BB + (tid & 127)] = 0ull;
    // Prefetch xg(0)
    {
        const float* src = g_xg + ((size_t)cta * 16) * BB;
        for (int e = tid; e < 512; e += P2_THREADS)
            cp_async16(xgs + e * 4, src + e * 4);
        cp_commit();
    }

    float cA = 0.f, cB = 0.f;   // cells for (h-col 2kpg, batch b), (2kpg+1, b)
    unsigned gen = 0;
    grid_barrier(++gen);

    for (int t = 0; t < TT; t++) {
        const ull* hsrc = g_hT_pk[t & 1];

        load_chunk(As, 0, hsrc, tid); cp_commit();
        load_chunk(As, 1, hsrc, tid); cp_commit();

        ull acc[64];
        #pragma unroll
        for (int i = 0; i < 64; i++) acc[i] = 0ull;

        #pragma unroll 1
        for (int ci = 0; ci < NCH; ci++) {
            if (ci < NCH - 2) {
                load_chunk(As, ci + 2, hsrc, tid);
                cp_commit();
            } else if (ci == NCH - 2) {
                if (t + 1 < TT) {
                    const float* src = g_xg + ((size_t)(t + 1) * G4H + cta * 16) * BB;
                    float* xdst = xgs + ((t + 1) & 1) * 2048;
                    for (int e = tid; e < 512; e += P2_THREADS)
                        cp_async16(xdst + e * 4, src + e * 4);
                }
                cp_commit();
            }
            if (ci == NCH - 1) cp_wait<1>(); else cp_wait<2>();
            __syncthreads();

            const ull* Ab = As + (ci & 3) * (KPC * AST);
            #pragma unroll
            for (int jj = 0; jj < 4; jj++) {
                const int kpl = jj * 8 + kps;
                const ull* ap = Ab + kpl * AST + bg * 8;
                const ull* wp = wsm + (ci * KPC + kpl) * WST + rg * 8;
                ulonglong2 a01 = *(const ulonglong2*)(ap + 0);
                ulonglong2 a23 = *(const ulonglong2*)(ap + 2);
                ulonglong2 a45 = *(const ulonglong2*)(ap + 4);
                ulonglong2 a67 = *(const ulonglong2*)(ap + 6);
                ulonglong2 w01 = *(const ulonglong2*)(wp + 0);
                ulonglong2 w23 = *(const ulonglong2*)(wp + 2);
                ulonglong2 w45 = *(const ulonglong2*)(wp + 4);
                ulonglong2 w67 = *(const ulonglong2*)(wp + 6);
                ull av[8] = {a01.x, a01.y, a23.x, a23.y, a45.x, a45.y, a67.x, a67.y};
                ull wv[8] = {w01.x, w01.y, w23.x, w23.y, w45.x, w45.y, w67.x, w67.y};
                #pragma unroll
                for (int ri = 0; ri < 8; ri++)
                    #pragma unroll
                    for (int bi = 0; bi < 8; bi++)
                        fma2(acc[ri * 8 + bi], av[bi], wv[ri]);
            }
        }

        // ---- fold k-parity, then selective 3-round shfl reduction over kps ----
        float v64[64];
        #pragma unroll
        for (int i = 0; i < 64; i++) {
            float lo, hi; unpack2(lo, hi, acc[i]);
            v64[i] = lo + hi;
        }
        const bool k0 = (kps & 1), k1 = (kps & 2), k2 = (kps & 4);
        float v32[32];
        #pragma unroll
        for (int ri = 0; ri < 8; ri++)
            #pragma unroll
            for (int bh = 0; bh < 4; bh++) {
                float keep = k0 ? v64[ri * 8 + 2 * bh + 1] : v64[ri * 8 + 2 * bh];
                float send = k0 ? v64[ri * 8 + 2 * bh]     : v64[ri * 8 + 2 * bh + 1];
                v32[ri * 4 + bh] = keep + __shfl_xor_sync(0xffffffffu, send, 1);
            }
        float v16[16];
        #pragma unroll
        for (int ri = 0; ri < 8; ri++)
            #pragma unroll
            for (int bq = 0; bq < 2; bq++) {
                float keep = k1 ? v32[ri * 4 + 2 * bq + 1] : v32[ri * 4 + 2 * bq];
                float send = k1 ? v32[ri * 4 + 2 * bq]     : v32[ri * 4 + 2 * bq + 1];
                v16[ri * 2 + bq] = keep + __shfl_xor_sync(0xffffffffu, send, 2);
            }
        float v8[8];
        #pragma unroll
        for (int ri = 0; ri < 8; ri++) {
            float keep = k2 ? v16[ri * 2 + 1] : v16[ri * 2 + 0];
            float send = k2 ? v16[ri * 2 + 0] : v16[ri * 2 + 1];
            v8[ri] = keep + __shfl_xor_sync(0xffffffffu, send, 4);
        }
        // v8[ri] = full gate sum for (row rg*8+ri, batch b); ri = hcl*4 + gate

        const float* xc = xgs + (t & 1) * 2048 + b;
        float ig = sigf (v8[0] + xc[(rg * 8 + 0) * BB]);
        float fg = sigf (v8[1] + xc[(rg * 8 + 1) * BB]);
        float gg = tanhf(v8[2] + xc[(rg * 8 + 2) * BB]);
        float og = sigf (v8[3] + xc[(rg * 8 + 3) * BB]);
        cA = fg * cA + ig * gg;
        float h0 = og * tanhf(cA);
        ig = sigf (v8[4] + xc[(rg * 8 + 4) * BB]);
        fg = sigf (v8[5] + xc[(rg * 8 + 5) * BB]);
        gg = tanhf(v8[6] + xc[(rg * 8 + 6) * BB]);
        og = sigf (v8[7] + xc[(rg * 8 + 7) * BB]);
        cB = fg * cB + ig * gg;
        float h1 = og * tanhf(cB);

        if (t < TT - 1) {
            g_hT_pk[(t + 1) & 1][kpg * BB + b] = pack2(h0, h1);
            grid_barrier(++gen);
        } else {
            *(float2*)(out + (size_t)b * HH + cta * 4 + rg * 2) = make_float2(h0, h1);
        }
    }
}

extern "C" void kernel_launch(void* const* d_in, const int* in_sizes, int n_in,
                              void* d_out, int out_size) {
    const float* x    = (const float*)d_in[0];
    const float* W_ih = (const float*)d_in[1];
    const float* W_hh = (const float*)d_in[2];
    const float* b_ih = (const float*)d_in[3];
    const float* b_hh = (const float*)d_in[4];
    float* out = (float*)d_out;

    const int p1_smem = BB * XS_STRIDE * 8;                               // 133,120
    const int p2_smem = (KPT * WST + NBUF * KPC * AST) * 8 + 2 * 16 * BB * 4; // 186,368
    cudaFuncSetAttribute(xgate_kernel,
                         cudaFuncAttributeMaxDynamicSharedMemorySize, p1_smem);
    cudaFuncSetAttribute(lstm_kernel,
                         cudaFuncAttributeMaxDynamicSharedMemorySize, p2_smem);

    xgate_kernel<<<dim3(16, TT), P1_THREADS, p1_smem>>>(x, W_ih, b_ih, b_hh);
    lstm_kernel<<<P2_GRID, P2_THREADS, p2_smem>>>(W_hh, out);
}